// round 1
// baseline (speedup 1.0000x reference)
#include <cuda_runtime.h>
#include <cuda_bf16.h>
#include <cstddef>

#define N_NODES 100000
#define N_EDGES 1600000
#define N_GRAPHS 4096
#define HID 512

// ---------------- scratch (device globals; allocation-free) ----------------
__device__ float g_h[(size_t)N_NODES * HID];    // current node features
__device__ float g_t[(size_t)N_NODES * HID];    // h + aggregated neighbors
__device__ float g_m[(size_t)N_NODES * HID];    // MLP hidden
__device__ float g_h7[(size_t)N_NODES * 7];     // layer-1 agg buffer (x + sum x[src])
__device__ float g_pool[(size_t)N_GRAPHS * HID];
__device__ float g_p1[(size_t)N_GRAPHS * 256];
__device__ int   g_cnt[N_GRAPHS];

// ---------------- helpers ----------------
__global__ void copy_x7(const float* __restrict__ x) {
    int i = blockIdx.x * blockDim.x + threadIdx.x;
    if (i < N_NODES * 7) g_h7[i] = x[i];
}

__global__ void edge_agg7(const int* __restrict__ src, const int* __restrict__ dst,
                          const float* __restrict__ x) {
    long long t = (long long)blockIdx.x * blockDim.x + threadIdx.x;
    int e = (int)(t >> 3);
    int k = (int)(t & 7);
    if (e >= N_EDGES || k >= 7) return;
    atomicAdd(&g_h7[(size_t)dst[e] * 7 + k], x[(size_t)src[e] * 7 + k]);
}

// g_m = relu(g_h7 @ w1 + b1), w1: [7,512]
__global__ __launch_bounds__(256) void mlp_in7(const float* __restrict__ w,
                                               const float* __restrict__ bias) {
    __shared__ float sw[7][512];
    __shared__ float sb[512];
    for (int i = threadIdx.x; i < 7 * 512; i += 256) ((float*)sw)[i] = w[i];
    for (int i = threadIdx.x; i < 512; i += 256) sb[i] = bias[i];
    __syncthreads();
    for (int r = blockIdx.x; r < N_NODES; r += gridDim.x) {
        float h[7];
#pragma unroll
        for (int k = 0; k < 7; k++) h[k] = g_h7[(size_t)r * 7 + k];
#pragma unroll
        for (int jj = 0; jj < 2; jj++) {
            int j = threadIdx.x + jj * 256;
            float acc = sb[j];
#pragma unroll
            for (int k = 0; k < 7; k++) acc = fmaf(h[k], sw[k][j], acc);
            g_m[(size_t)r * 512 + j] = fmaxf(acc, 0.f);
        }
    }
}

// warp-per-edge: g_t[dst] += g_h[src]  (512 f32 = 128 float4)
__global__ void edge_agg512(const int* __restrict__ src, const int* __restrict__ dst) {
    int w = (int)(((long long)blockIdx.x * blockDim.x + threadIdx.x) >> 5);
    int lane = threadIdx.x & 31;
    if (w >= N_EDGES) return;
    int s = src[w], d = dst[w];
    const float4* xs = (const float4*)(g_h + (size_t)s * HID);
    float4* xd = (float4*)(g_t + (size_t)d * HID);
#pragma unroll
    for (int i = 0; i < 4; i++) {
        float4 v = xs[lane + 32 * i];
#if __CUDA_ARCH__ >= 900
        atomicAdd(xd + lane + 32 * i, v);
#else
        float* p = (float*)(xd + lane + 32 * i);
        atomicAdd(p + 0, v.x); atomicAdd(p + 1, v.y);
        atomicAdd(p + 2, v.z); atomicAdd(p + 3, v.w);
#endif
    }
}

// ---------------- SGEMM: C[M,N] = relu?(A[M,K] @ B[K,N] + bias), optional dup-store ----------------
#define BM 128
#define BN 128
#define BKK 8

template <bool RELU, bool DUP>
__global__ __launch_bounds__(256, 2) void sgemm128(
    int M, int N, int K,
    const float* __restrict__ A, const float* __restrict__ B,
    const float* __restrict__ bias,
    float* __restrict__ C, float* __restrict__ C2) {
    __shared__ float As[BKK][BM + 4];
    __shared__ float Bs[BKK][BN];

    const int tid = threadIdx.x;
    const int bx = blockIdx.x;  // N block
    const int by = blockIdx.y;  // M block

    const int a_r = tid >> 1;            // 0..127
    const int a_c = (tid & 1) << 2;      // 0,4
    const int b_r = tid >> 5;            // 0..7
    const int b_c = (tid & 31) << 2;     // 0..124

    const int g_arow = by * BM + a_r;
    const bool a_ok = g_arow < M;
    const float* Aptr = A + (size_t)g_arow * K + a_c;
    const float* Bptr = B + (size_t)b_r * N + bx * BN + b_c;

    const int trow = tid >> 4;  // 0..15
    const int tcol = tid & 15;  // 0..15

    float acc[8][8];
#pragma unroll
    for (int i = 0; i < 8; i++)
#pragma unroll
        for (int j = 0; j < 8; j++) acc[i][j] = 0.f;

    for (int k0 = 0; k0 < K; k0 += BKK) {
        float4 av = a_ok ? *(const float4*)Aptr : make_float4(0.f, 0.f, 0.f, 0.f);
        As[a_c + 0][a_r] = av.x;
        As[a_c + 1][a_r] = av.y;
        As[a_c + 2][a_r] = av.z;
        As[a_c + 3][a_r] = av.w;
        *(float4*)&Bs[b_r][b_c] = *(const float4*)Bptr;
        __syncthreads();
#pragma unroll
        for (int k = 0; k < BKK; k++) {
            float4 a0 = *(const float4*)&As[k][trow * 4];
            float4 a1 = *(const float4*)&As[k][64 + trow * 4];
            float4 b0 = *(const float4*)&Bs[k][tcol * 4];
            float4 b1 = *(const float4*)&Bs[k][64 + tcol * 4];
            float ar[8] = {a0.x, a0.y, a0.z, a0.w, a1.x, a1.y, a1.z, a1.w};
            float br[8] = {b0.x, b0.y, b0.z, b0.w, b1.x, b1.y, b1.z, b1.w};
#pragma unroll
            for (int i = 0; i < 8; i++)
#pragma unroll
                for (int j = 0; j < 8; j++) acc[i][j] = fmaf(ar[i], br[j], acc[i][j]);
        }
        __syncthreads();
        Aptr += BKK;
        Bptr += (size_t)BKK * N;
    }

#pragma unroll
    for (int i = 0; i < 8; i++) {
        int lr = (i < 4) ? (trow * 4 + i) : (64 + trow * 4 + (i - 4));
        int r = by * BM + lr;
        if (r >= M) continue;
#pragma unroll
        for (int jh = 0; jh < 2; jh++) {
            int lc = jh * 64 + tcol * 4;
            int c = bx * BN + lc;
            float4 v;
            v.x = acc[i][jh * 4 + 0] + bias[c + 0];
            v.y = acc[i][jh * 4 + 1] + bias[c + 1];
            v.z = acc[i][jh * 4 + 2] + bias[c + 2];
            v.w = acc[i][jh * 4 + 3] + bias[c + 3];
            if (RELU) {
                v.x = fmaxf(v.x, 0.f); v.y = fmaxf(v.y, 0.f);
                v.z = fmaxf(v.z, 0.f); v.w = fmaxf(v.w, 0.f);
            }
            *(float4*)&C[(size_t)r * N + c] = v;
            if (DUP) *(float4*)&C2[(size_t)r * N + c] = v;
        }
    }
}

// ---------------- pooling + head ----------------
__global__ void zero_pool() {
    int i = blockIdx.x * blockDim.x + threadIdx.x;
    if (i < N_GRAPHS * HID) g_pool[i] = 0.f;
    if (i < N_GRAPHS) g_cnt[i] = 0;
}

__global__ void pool_sum(const int* __restrict__ batch) {
    long long t = (long long)blockIdx.x * blockDim.x + threadIdx.x;
    int node = (int)(t >> 7);
    int f4 = (int)(t & 127);
    if (node >= N_NODES) return;
    int g = batch[node];
    float4 v = *(const float4*)&g_h[(size_t)node * HID + f4 * 4];
#if __CUDA_ARCH__ >= 900
    atomicAdd((float4*)&g_pool[(size_t)g * HID + f4 * 4], v);
#else
    float* p = &g_pool[(size_t)g * HID + f4 * 4];
    atomicAdd(p + 0, v.x); atomicAdd(p + 1, v.y);
    atomicAdd(p + 2, v.z); atomicAdd(p + 3, v.w);
#endif
    if (f4 == 0) atomicAdd(&g_cnt[g], 1);
}

__global__ void pool_div() {
    int i = blockIdx.x * blockDim.x + threadIdx.x;
    if (i >= N_GRAPHS * HID) return;
    int g = i >> 9;
    float c = (float)g_cnt[g];
    g_pool[i] = g_pool[i] / fmaxf(c, 1.f);
}

// out[4096,12] = g_p1[4096,256] @ w[256,12] + b
__global__ void head2(const float* __restrict__ w, const float* __restrict__ b,
                      float* __restrict__ out) {
    int g = blockIdx.x;
    int o = threadIdx.x;
    if (o >= 12) return;
    float acc = b[o];
    const float* row = g_p1 + (size_t)g * 256;
#pragma unroll 8
    for (int k = 0; k < 256; k++) acc = fmaf(row[k], w[k * 12 + o], acc);
    out[(size_t)g * 12 + o] = acc;
}

// ---------------- launch ----------------
extern "C" void kernel_launch(void* const* d_in, const int* in_sizes, int n_in,
                              void* d_out, int out_size) {
    const float* x = (const float*)d_in[0];
    const int* ei = (const int*)d_in[1];
    const int* src = ei;
    const int* dst = ei + N_EDGES;
    const int* batch = (const int*)d_in[2];
    const float* c1w1 = (const float*)d_in[3];
    const float* c1b1 = (const float*)d_in[4];
    const float* c1w2 = (const float*)d_in[5];
    const float* c1b2 = (const float*)d_in[6];
    const float* c2w1 = (const float*)d_in[7];
    const float* c2b1 = (const float*)d_in[8];
    const float* c2w2 = (const float*)d_in[9];
    const float* c2b2 = (const float*)d_in[10];
    const float* c3w1 = (const float*)d_in[11];
    const float* c3b1 = (const float*)d_in[12];
    const float* c3w2 = (const float*)d_in[13];
    const float* c3b2 = (const float*)d_in[14];
    const float* lw1 = (const float*)d_in[15];
    const float* lb1 = (const float*)d_in[16];
    const float* lw2 = (const float*)d_in[17];
    const float* lb2 = (const float*)d_in[18];
    float* out = (float*)d_out;

    float *p_h, *p_t, *p_m, *p_pool, *p_p1;
    cudaGetSymbolAddress((void**)&p_h, g_h);
    cudaGetSymbolAddress((void**)&p_t, g_t);
    cudaGetSymbolAddress((void**)&p_m, g_m);
    cudaGetSymbolAddress((void**)&p_pool, g_pool);
    cudaGetSymbolAddress((void**)&p_p1, g_p1);

    const dim3 gemm_grid(HID / BN, (N_NODES + BM - 1) / BM);   // (4, 782)
    const dim3 head_grid(256 / BN, N_GRAPHS / BM);             // (2, 32)

    // ---- layer 1 ----
    copy_x7<<<(N_NODES * 7 + 255) / 256, 256>>>(x);
    edge_agg7<<<(int)(((long long)N_EDGES * 8 + 255) / 256), 256>>>(src, dst, x);
    mlp_in7<<<2048, 256>>>(c1w1, c1b1);                                      // g_m
    sgemm128<true, true><<<gemm_grid, 256>>>(N_NODES, HID, HID, p_m, c1w2, c1b2, p_h, p_t);

    // ---- layer 2 ----
    edge_agg512<<<(int)(((long long)N_EDGES * 32 + 255) / 256), 256>>>(src, dst);
    sgemm128<true, false><<<gemm_grid, 256>>>(N_NODES, HID, HID, p_t, c2w1, c2b1, p_m, nullptr);
    sgemm128<true, true><<<gemm_grid, 256>>>(N_NODES, HID, HID, p_m, c2w2, c2b2, p_h, p_t);

    // ---- layer 3 ----
    edge_agg512<<<(int)(((long long)N_EDGES * 32 + 255) / 256), 256>>>(src, dst);
    sgemm128<true, false><<<gemm_grid, 256>>>(N_NODES, HID, HID, p_t, c3w1, c3b1, p_m, nullptr);
    sgemm128<true, false><<<gemm_grid, 256>>>(N_NODES, HID, HID, p_m, c3w2, c3b2, p_h, nullptr);

    // ---- mean pool ----
    zero_pool<<<(N_GRAPHS * HID + 255) / 256, 256>>>();
    pool_sum<<<(int)(((long long)N_NODES * 128 + 255) / 256), 256>>>(batch);
    pool_div<<<(N_GRAPHS * HID + 255) / 256, 256>>>();

    // ---- head ----
    sgemm128<true, false><<<head_grid, 256>>>(N_GRAPHS, 256, HID, p_pool, lw1, lb1, p_p1, nullptr);
    head2<<<N_GRAPHS, 32>>>(lw2, lb2, out);
}

// round 2
// speedup vs baseline: 1.8049x; 1.8049x over previous
#include <cuda_runtime.h>
#include <cuda_bf16.h>
#include <cstdint>
#include <cstddef>

#define N_NODES 100000
#define N_EDGES 1600000
#define N_GRAPHS 4096
#define HID 512

// ---------------- scratch (device globals; allocation-free) ----------------
__device__ float g_h[(size_t)N_NODES * HID];    // current node features
__device__ float g_t[(size_t)N_NODES * HID];    // h + aggregated neighbors
__device__ float g_m[(size_t)N_NODES * HID];    // MLP hidden
__device__ float g_h7[(size_t)N_NODES * 7];     // layer-1 agg buffer (x + sum x[src])
__device__ float g_pool[(size_t)N_GRAPHS * HID];
__device__ float g_p1[(size_t)N_GRAPHS * 256];
__device__ int   g_cnt[N_GRAPHS];

// ---------------- helpers ----------------
__global__ void copy_x7(const float* __restrict__ x) {
    int i = blockIdx.x * blockDim.x + threadIdx.x;
    if (i < N_NODES * 7) g_h7[i] = x[i];
}

__global__ void edge_agg7(const int* __restrict__ src, const int* __restrict__ dst,
                          const float* __restrict__ x) {
    long long t = (long long)blockIdx.x * blockDim.x + threadIdx.x;
    int e = (int)(t >> 3);
    int k = (int)(t & 7);
    if (e >= N_EDGES || k >= 7) return;
    atomicAdd(&g_h7[(size_t)dst[e] * 7 + k], x[(size_t)src[e] * 7 + k]);
}

// g_m = relu(g_h7 @ w1 + b1), w1: [7,512]  (exact fp32)
__global__ __launch_bounds__(256) void mlp_in7(const float* __restrict__ w,
                                               const float* __restrict__ bias) {
    __shared__ float sw[7][512];
    __shared__ float sb[512];
    for (int i = threadIdx.x; i < 7 * 512; i += 256) ((float*)sw)[i] = w[i];
    for (int i = threadIdx.x; i < 512; i += 256) sb[i] = bias[i];
    __syncthreads();
    for (int r = blockIdx.x; r < N_NODES; r += gridDim.x) {
        float h[7];
#pragma unroll
        for (int k = 0; k < 7; k++) h[k] = g_h7[(size_t)r * 7 + k];
#pragma unroll
        for (int jj = 0; jj < 2; jj++) {
            int j = threadIdx.x + jj * 256;
            float acc = sb[j];
#pragma unroll
            for (int k = 0; k < 7; k++) acc = fmaf(h[k], sw[k][j], acc);
            g_m[(size_t)r * 512 + j] = fmaxf(acc, 0.f);
        }
    }
}

// warp-per-edge: g_t[dst] += g_h[src]  (512 f32 = 128 float4)
__global__ void edge_agg512(const int* __restrict__ src, const int* __restrict__ dst) {
    int w = (int)(((long long)blockIdx.x * blockDim.x + threadIdx.x) >> 5);
    int lane = threadIdx.x & 31;
    if (w >= N_EDGES) return;
    int s = src[w], d = dst[w];
    const float4* xs = (const float4*)(g_h + (size_t)s * HID);
    float4* xd = (float4*)(g_t + (size_t)d * HID);
#pragma unroll
    for (int i = 0; i < 4; i++) {
        float4 v = xs[lane + 32 * i];
        atomicAdd(xd + lane + 32 * i, v);
    }
}

// ---------------- TF32 tensor-core GEMM ----------------
// C[M,N] = relu?(A[M,K] @ B[K,N] + bias), optional dup-store to C2.
// Block tile 128x128, 8 warps of 64x32, K-chunk 32 (4 k8 steps).
// SMEM holds fragment-permuted tf32 tiles: one ld.shared.v4 per A-frag,
// one ld.shared.v2 per B-frag, conflict-free.

__device__ __forceinline__ uint32_t f2tf32(float x) {
    uint32_t r;
    asm("cvt.rna.tf32.f32 %0, %1;" : "=r"(r) : "f"(x));
    return r;
}

__device__ __forceinline__ void mma1688(float* d, const uint32_t* a, const uint32_t* b) {
    asm volatile(
        "mma.sync.aligned.m16n8k8.row.col.f32.tf32.tf32.f32 "
        "{%0,%1,%2,%3},{%4,%5,%6,%7},{%8,%9},{%0,%1,%2,%3};\n"
        : "+f"(d[0]), "+f"(d[1]), "+f"(d[2]), "+f"(d[3])
        : "r"(a[0]), "r"(a[1]), "r"(a[2]), "r"(a[3]), "r"(b[0]), "r"(b[1]));
}

template <bool RELU, bool DUP>
__global__ __launch_bounds__(256, 2) void gemm_tf32(
    int M, int N, int K, int lda, int ldb, int ldc,
    const float* __restrict__ A, const float* __restrict__ B,
    const float* __restrict__ bias,
    float* __restrict__ C, float* __restrict__ C2) {
    __shared__ uint32_t sA[4096];  // 8 m16-tiles x 4 k8-tiles x 128
    __shared__ uint32_t sB[4096];  // 16 n8-tiles x 4 k8-tiles x 64

    const int tid = threadIdx.x;
    const int lane = tid & 31;
    const int warp = tid >> 5;
    const int wy = warp & 1;   // 0..1 -> m offset 0/64
    const int wx = warp >> 1;  // 0..3 -> n offset 0/32/64/96

    const int m0 = blockIdx.y * 128;
    const int n0 = blockIdx.x * 128;

    // --- staging thread mapping ---
    const int a_row = tid >> 1;             // 0..127
    const int a_cb = (tid & 1) << 4;        // 0 or 16
    const bool a_ok = (m0 + a_row) < M;
    const float* Abase = A + (size_t)(m0 + a_row) * lda + a_cb;
    const int a_tm = a_row >> 4;
    const int a_r16 = a_row & 15;

    const int b_row = tid >> 3;             // 0..31
    const int b_cb = (tid & 7) << 4;        // 0..112
    const float* Bbase = B + (size_t)b_row * ldb + n0 + b_cb;
    const int b_tk = b_row >> 3;            // 0..3
    const int b_k8 = b_row & 7;

    float4 apf[4], bpf[4];
    const float4 z4 = make_float4(0.f, 0.f, 0.f, 0.f);

    // prologue load (k0 = 0)
#pragma unroll
    for (int q = 0; q < 4; q++) {
        apf[q] = a_ok ? *(const float4*)(Abase + q * 4) : z4;
        bpf[q] = *(const float4*)(Bbase + q * 4);
    }

    auto store_stage = [&]() {
#pragma unroll
        for (int q = 0; q < 4; q++) {
            const float av[4] = {apf[q].x, apf[q].y, apf[q].z, apf[q].w};
            const float bv[4] = {bpf[q].x, bpf[q].y, bpf[q].z, bpf[q].w};
#pragma unroll
            for (int u = 0; u < 4; u++) {
                {
                    int col = a_cb + q * 4 + u;
                    int tk = col >> 3, c8 = col & 7;
                    int blob = ((a_r16 & 7) * 4 + (c8 & 3)) * 4 + (a_r16 >> 3) + 2 * (c8 >> 2);
                    sA[(a_tm * 4 + tk) * 128 + blob] = f2tf32(av[u]);
                }
                {
                    int col = b_cb + q * 4 + u;
                    int tn = col >> 3, n8 = col & 7;
                    int blob = (n8 * 4 + (b_k8 & 3)) * 2 + (b_k8 >> 2);
                    sB[(tn * 4 + b_tk) * 64 + blob] = f2tf32(bv[u]);
                }
            }
        }
    };

    store_stage();
    __syncthreads();

    float acc[4][4][4];
#pragma unroll
    for (int i = 0; i < 4; i++)
#pragma unroll
        for (int j = 0; j < 4; j++)
#pragma unroll
            for (int r = 0; r < 4; r++) acc[i][j][r] = 0.f;

    const int nks = K >> 5;  // K/32
    for (int ks = 0; ks < nks; ks++) {
        // prefetch next stage into regs
        if (ks + 1 < nks) {
            const float* An = Abase + (ks + 1) * 32;
            const float* Bn = Bbase + (size_t)(ks + 1) * 32 * ldb;
#pragma unroll
            for (int q = 0; q < 4; q++) {
                apf[q] = a_ok ? *(const float4*)(An + q * 4) : z4;
                bpf[q] = *(const float4*)(Bn + q * 4);
            }
        }

        // compute from smem
#pragma unroll
        for (int kk = 0; kk < 4; kk++) {
            uint4 af[4];
            uint2 bf[4];
#pragma unroll
            for (int i = 0; i < 4; i++)
                af[i] = *(const uint4*)&sA[((wy * 4 + i) * 4 + kk) * 128 + (lane << 2)];
#pragma unroll
            for (int j = 0; j < 4; j++)
                bf[j] = *(const uint2*)&sB[((wx * 4 + j) * 4 + kk) * 64 + (lane << 1)];
#pragma unroll
            for (int i = 0; i < 4; i++)
#pragma unroll
                for (int j = 0; j < 4; j++)
                    mma1688(acc[i][j], (const uint32_t*)&af[i], (const uint32_t*)&bf[j]);
        }
        __syncthreads();
        if (ks + 1 < nks) {
            store_stage();
            __syncthreads();
        }
    }

    // --- epilogue: bias (+relu) (+dup) ---
    const int crow = lane >> 2;          // 0..7
    const int ccol = (lane & 3) << 1;    // 0,2,4,6
#pragma unroll
    for (int i = 0; i < 4; i++) {
        int r0 = m0 + wy * 64 + i * 16 + crow;
        int r1 = r0 + 8;
#pragma unroll
        for (int j = 0; j < 4; j++) {
            int c = n0 + wx * 32 + j * 8 + ccol;
            float b0 = bias[c], b1 = bias[c + 1];
            float2 v0, v1;
            v0.x = acc[i][j][0] + b0; v0.y = acc[i][j][1] + b1;
            v1.x = acc[i][j][2] + b0; v1.y = acc[i][j][3] + b1;
            if (RELU) {
                v0.x = fmaxf(v0.x, 0.f); v0.y = fmaxf(v0.y, 0.f);
                v1.x = fmaxf(v1.x, 0.f); v1.y = fmaxf(v1.y, 0.f);
            }
            if (r0 < M) {
                *(float2*)&C[(size_t)r0 * ldc + c] = v0;
                if (DUP) *(float2*)&C2[(size_t)r0 * ldc + c] = v0;
            }
            if (r1 < M) {
                *(float2*)&C[(size_t)r1 * ldc + c] = v1;
                if (DUP) *(float2*)&C2[(size_t)r1 * ldc + c] = v1;
            }
        }
    }
}

// ---------------- pooling + head ----------------
__global__ void zero_pool() {
    int i = blockIdx.x * blockDim.x + threadIdx.x;
    if (i < N_GRAPHS * HID) g_pool[i] = 0.f;
    if (i < N_GRAPHS) g_cnt[i] = 0;
}

__global__ void pool_sum(const int* __restrict__ batch) {
    long long t = (long long)blockIdx.x * blockDim.x + threadIdx.x;
    int node = (int)(t >> 7);
    int f4 = (int)(t & 127);
    if (node >= N_NODES) return;
    int g = batch[node];
    float4 v = *(const float4*)&g_h[(size_t)node * HID + f4 * 4];
    atomicAdd((float4*)&g_pool[(size_t)g * HID + f4 * 4], v);
    if (f4 == 0) atomicAdd(&g_cnt[g], 1);
}

__global__ void pool_div() {
    int i = blockIdx.x * blockDim.x + threadIdx.x;
    if (i >= N_GRAPHS * HID) return;
    int g = i >> 9;
    float c = (float)g_cnt[g];
    g_pool[i] = g_pool[i] / fmaxf(c, 1.f);
}

// out[4096,12] = g_p1[4096,256] @ w[256,12] + b   (exact fp32)
__global__ void head2(const float* __restrict__ w, const float* __restrict__ b,
                      float* __restrict__ out) {
    int g = blockIdx.x;
    int o = threadIdx.x;
    if (o >= 12) return;
    float acc = b[o];
    const float* row = g_p1 + (size_t)g * 256;
#pragma unroll 8
    for (int k = 0; k < 256; k++) acc = fmaf(row[k], w[k * 12 + o], acc);
    out[(size_t)g * 12 + o] = acc;
}

// ---------------- launch ----------------
extern "C" void kernel_launch(void* const* d_in, const int* in_sizes, int n_in,
                              void* d_out, int out_size) {
    const float* x = (const float*)d_in[0];
    const int* ei = (const int*)d_in[1];
    const int* src = ei;
    const int* dst = ei + N_EDGES;
    const int* batch = (const int*)d_in[2];
    const float* c1w1 = (const float*)d_in[3];
    const float* c1b1 = (const float*)d_in[4];
    const float* c1w2 = (const float*)d_in[5];
    const float* c1b2 = (const float*)d_in[6];
    const float* c2w1 = (const float*)d_in[7];
    const float* c2b1 = (const float*)d_in[8];
    const float* c2w2 = (const float*)d_in[9];
    const float* c2b2 = (const float*)d_in[10];
    const float* c3w1 = (const float*)d_in[11];
    const float* c3b1 = (const float*)d_in[12];
    const float* c3w2 = (const float*)d_in[13];
    const float* c3b2 = (const float*)d_in[14];
    const float* lw1 = (const float*)d_in[15];
    const float* lb1 = (const float*)d_in[16];
    const float* lw2 = (const float*)d_in[17];
    const float* lb2 = (const float*)d_in[18];
    float* out = (float*)d_out;

    float *p_h, *p_t, *p_m, *p_pool, *p_p1;
    cudaGetSymbolAddress((void**)&p_h, g_h);
    cudaGetSymbolAddress((void**)&p_t, g_t);
    cudaGetSymbolAddress((void**)&p_m, g_m);
    cudaGetSymbolAddress((void**)&p_pool, g_pool);
    cudaGetSymbolAddress((void**)&p_p1, g_p1);

    const dim3 gg(HID / 128, (N_NODES + 127) / 128);   // (4, 782)
    const dim3 hg(256 / 128, N_GRAPHS / 128);          // (2, 32)

    // ---- layer 1 ----
    copy_x7<<<(N_NODES * 7 + 255) / 256, 256>>>(x);
    edge_agg7<<<(int)(((long long)N_EDGES * 8 + 255) / 256), 256>>>(src, dst, x);
    mlp_in7<<<2048, 256>>>(c1w1, c1b1);  // g_m (exact fp32)
    gemm_tf32<true, true><<<gg, 256>>>(N_NODES, HID, HID, HID, HID, HID, p_m, c1w2, c1b2, p_h, p_t);

    // ---- layer 2 ----
    edge_agg512<<<(int)(((long long)N_EDGES * 32 + 255) / 256), 256>>>(src, dst);
    gemm_tf32<true, false><<<gg, 256>>>(N_NODES, HID, HID, HID, HID, HID, p_t, c2w1, c2b1, p_m, nullptr);
    gemm_tf32<true, true><<<gg, 256>>>(N_NODES, HID, HID, HID, HID, HID, p_m, c2w2, c2b2, p_h, p_t);

    // ---- layer 3 ----
    edge_agg512<<<(int)(((long long)N_EDGES * 32 + 255) / 256), 256>>>(src, dst);
    gemm_tf32<true, false><<<gg, 256>>>(N_NODES, HID, HID, HID, HID, HID, p_t, c3w1, c3b1, p_m, nullptr);
    gemm_tf32<true, false><<<gg, 256>>>(N_NODES, HID, HID, HID, HID, HID, p_m, c3w2, c3b2, p_h, nullptr);

    // ---- mean pool ----
    zero_pool<<<(N_GRAPHS * HID + 255) / 256, 256>>>();
    pool_sum<<<(int)(((long long)N_NODES * 128 + 255) / 256), 256>>>(batch);
    pool_div<<<(N_GRAPHS * HID + 255) / 256, 256>>>();

    // ---- head ----
    gemm_tf32<true, false><<<hg, 256>>>(N_GRAPHS, 256, HID, HID, 256, 256, p_pool, lw1, lb1, p_p1, nullptr);
    head2<<<N_GRAPHS, 32>>>(lw2, lb2, out);
}

// round 5
// speedup vs baseline: 2.7898x; 1.5457x over previous
#include <cuda_runtime.h>
#include <cuda_bf16.h>
#include <cstdint>
#include <cstddef>

#define N_NODES 100000
#define N_EDGES 1600000
#define N_GRAPHS 4096
#define HID 512

// ---------------- scratch (device globals; allocation-free) ----------------
__device__ float g_h[(size_t)N_NODES * HID];
__device__ float g_t[(size_t)N_NODES * HID];
__device__ float g_m[(size_t)N_NODES * HID];
__device__ float g_h7[(size_t)N_NODES * 7];
__device__ float g_pool[(size_t)N_GRAPHS * HID];
__device__ float g_p1[(size_t)N_GRAPHS * 256];
__device__ int   g_cnt[N_GRAPHS];
__device__ float g_wt[5 * 512 * 512 + 256 * 512];  // [N,K] transposed tf32-rounded weights

__device__ __forceinline__ uint32_t f2tf32(float x) {
    uint32_t r;
    asm("cvt.rna.tf32.f32 %0, %1;" : "=r"(r) : "f"(x));
    return r;
}
__device__ __forceinline__ float roundtf(float x) { return __uint_as_float(f2tf32(x)); }

// ---------------- small helpers ----------------
__global__ void copy_x7(const float* __restrict__ x) {
    int i = blockIdx.x * blockDim.x + threadIdx.x;
    if (i < N_NODES * 7) g_h7[i] = x[i];
}

__global__ void edge_agg7(const int* __restrict__ src, const int* __restrict__ dst,
                          const float* __restrict__ x) {
    long long t = (long long)blockIdx.x * blockDim.x + threadIdx.x;
    int e = (int)(t >> 3);
    int k = (int)(t & 7);
    if (e >= N_EDGES || k >= 7) return;
    atomicAdd(&g_h7[(size_t)dst[e] * 7 + k], x[(size_t)src[e] * 7 + k]);
}

// g_m = round_tf32(relu(g_h7 @ w1 + b1)) — exact fp32 math, tf32-rounded store
__global__ __launch_bounds__(256) void mlp_in7(const float* __restrict__ w,
                                               const float* __restrict__ bias) {
    __shared__ float sw[7][512];
    __shared__ float sb[512];
    for (int i = threadIdx.x; i < 7 * 512; i += 256) ((float*)sw)[i] = w[i];
    for (int i = threadIdx.x; i < 512; i += 256) sb[i] = bias[i];
    __syncthreads();
    for (int r = blockIdx.x; r < N_NODES; r += gridDim.x) {
        float h[7];
#pragma unroll
        for (int k = 0; k < 7; k++) h[k] = g_h7[(size_t)r * 7 + k];
#pragma unroll
        for (int jj = 0; jj < 2; jj++) {
            int j = threadIdx.x + jj * 256;
            float acc = sb[j];
#pragma unroll
            for (int k = 0; k < 7; k++) acc = fmaf(h[k], sw[k][j], acc);
            g_m[(size_t)r * 512 + j] = roundtf(fmaxf(acc, 0.f));
        }
    }
}

__global__ void edge_agg512(const int* __restrict__ src, const int* __restrict__ dst) {
    int w = (int)(((long long)blockIdx.x * blockDim.x + threadIdx.x) >> 5);
    int lane = threadIdx.x & 31;
    if (w >= N_EDGES) return;
    int s = src[w], d = dst[w];
    const float4* xs = (const float4*)(g_h + (size_t)s * HID);
    float4* xd = (float4*)(g_t + (size_t)d * HID);
#pragma unroll
    for (int i = 0; i < 4; i++) {
        float4 v = xs[lane + 32 * i];
        atomicAdd(xd + lane + 32 * i, v);
    }
}

// round g_t to tf32 values (so GEMM truncation is exact)
__global__ void round_t() {
    size_t i = (size_t)blockIdx.x * blockDim.x + threadIdx.x;
    if (i >= (size_t)N_NODES * HID / 4) return;
    float4 v = ((float4*)g_t)[i];
    v.x = roundtf(v.x); v.y = roundtf(v.y);
    v.z = roundtf(v.z); v.w = roundtf(v.w);
    ((float4*)g_t)[i] = v;
}

// transpose [K,N] -> [N,K], tf32-round
__global__ void transposeKN(const float* __restrict__ in, float* __restrict__ outp,
                            int K, int N) {
    __shared__ float t[32][33];
    int n0 = blockIdx.x * 32, k0 = blockIdx.y * 32;
    int tx = threadIdx.x, ty = threadIdx.y;  // block (32,8)
#pragma unroll
    for (int i = 0; i < 4; i++)
        t[ty + i * 8][tx] = in[(size_t)(k0 + ty + i * 8) * N + n0 + tx];
    __syncthreads();
#pragma unroll
    for (int i = 0; i < 4; i++)
        outp[(size_t)(n0 + ty + i * 8) * K + k0 + tx] = roundtf(t[tx][ty + i * 8]);
}

// ---------------- TF32 mma.sync GEMM, cp.async 3-stage pipeline ----------------
// C[M,n0:n0+128] = relu(A[M,K] @ Bt[n0:,K]^T + bias). All inputs tf32-valued.
// Tiles: BM=128, BN=128, BK=32, 3 stages, 8 warps (warp tile 64x32).
// SMEM: per stage A[128][32] + B[128][32] floats with 16B-chunk XOR swizzle:
//   word(r,c) = r*32 + ((c>>2) ^ (r&7))*4 + (c&3)   -> conflict-free scalar LDS.

#define STG_WORDS 8192           // 4096 A + 4096 B floats per stage
#define STG_BYTES (STG_WORDS * 4)
#define GSM_BYTES (3 * STG_BYTES)  // 96 KB

__device__ __forceinline__ void cp16(uint32_t dst, const void* src, int sz) {
    asm volatile("cp.async.cg.shared.global [%0], [%1], 16, %2;"
                 :: "r"(dst), "l"(src), "r"(sz));
}

__device__ __forceinline__ void mma1688(float* d, const float* a, const float* b) {
    asm volatile(
        "mma.sync.aligned.m16n8k8.row.col.f32.tf32.tf32.f32 "
        "{%0,%1,%2,%3},{%4,%5,%6,%7},{%8,%9},{%0,%1,%2,%3};\n"
        : "+f"(d[0]), "+f"(d[1]), "+f"(d[2]), "+f"(d[3])
        : "r"(__float_as_uint(a[0])), "r"(__float_as_uint(a[1])),
          "r"(__float_as_uint(a[2])), "r"(__float_as_uint(a[3])),
          "r"(__float_as_uint(b[0])), "r"(__float_as_uint(b[1])));
}

template <bool ROUND_OUT, bool DUP>
__global__ __launch_bounds__(256) void gemm_ca(
    int M, int K, int ldc,
    const float* __restrict__ A, const float* __restrict__ Bt,
    const float* __restrict__ bias,
    float* __restrict__ C, float* __restrict__ C2) {
    extern __shared__ __align__(128) float smf[];
    uint32_t smem_u32;
    asm("{ .reg .u64 t; cvta.to.shared.u64 t, %1; cvt.u32.u64 %0, t; }"
        : "=r"(smem_u32) : "l"(smf));

    const int tid = threadIdx.x;
    const int lane = tid & 31;
    const int warp = tid >> 5;
    const int wy = warp & 1;   // m offset 0/64
    const int wx = warp >> 1;  // n offset 0/32/64/96
    const int m0 = blockIdx.y * 128;
    const int n0 = blockIdx.x * 128;

    const int cprow = tid >> 3;       // 0..31 (row step 32 per q)
    const int cpc4 = tid & 7;         // 16B chunk 0..7
    const int cpswz = (cpc4 ^ (cprow & 7)) << 2;  // (row&7) invariant under +32

    const int nks = K >> 5;

    auto issue = [&](int ks) {
        uint32_t sa = smem_u32 + (uint32_t)(ks % 3) * STG_BYTES;
        uint32_t sb = sa + 16384;
#pragma unroll
        for (int q = 0; q < 4; q++) {
            int row = cprow + q * 32;
            int grow = m0 + row;
            const float* src = A + (size_t)(grow < M ? grow : 0) * K + ks * 32 + cpc4 * 4;
            cp16(sa + (uint32_t)(row * 32 + cpswz) * 4, src, grow < M ? 16 : 0);
        }
#pragma unroll
        for (int q = 0; q < 4; q++) {
            int row = cprow + q * 32;
            const float* src = Bt + (size_t)(n0 + row) * K + ks * 32 + cpc4 * 4;
            cp16(sb + (uint32_t)(row * 32 + cpswz) * 4, src, 16);
        }
        asm volatile("cp.async.commit_group;");
    };

    issue(0);
    issue(1);

    float acc[4][4][4];
#pragma unroll
    for (int i = 0; i < 4; i++)
#pragma unroll
        for (int j = 0; j < 4; j++)
#pragma unroll
            for (int r = 0; r < 4; r++) acc[i][j][r] = 0.f;

    const int r8 = lane >> 2;   // 0..7
    const int c3 = lane & 3;    // 0..3

    for (int ks = 0; ks < nks; ks++) {
        if (ks + 2 < nks) issue(ks + 2);
        else asm volatile("cp.async.commit_group;");
        asm volatile("cp.async.wait_group %0;" :: "n"(2));
        __syncthreads();

        const float* sA = smf + (ks % 3) * STG_WORDS;
        const float* sB = sA + 4096;
#pragma unroll
        for (int kk = 0; kk < 4; kk++) {
            float a[4][4];
#pragma unroll
            for (int i = 0; i < 4; i++) {
                int row = wy * 64 + i * 16 + r8;
                int base = row * 32;
                int ch0 = ((kk * 2) ^ r8) * 4 + c3;
                int ch1 = ((kk * 2 + 1) ^ r8) * 4 + c3;
                a[i][0] = sA[base + ch0];
                a[i][1] = sA[base + 256 + ch0];
                a[i][2] = sA[base + ch1];
                a[i][3] = sA[base + 256 + ch1];
            }
            float b[4][2];
#pragma unroll
            for (int j = 0; j < 4; j++) {
                int n = wx * 32 + j * 8 + r8;
                int base = n * 32;
                b[j][0] = sB[base + ((kk * 2) ^ r8) * 4 + c3];
                b[j][1] = sB[base + ((kk * 2 + 1) ^ r8) * 4 + c3];
            }
#pragma unroll
            for (int i = 0; i < 4; i++)
#pragma unroll
                for (int j = 0; j < 4; j++) mma1688(acc[i][j], a[i], b[j]);
        }
        __syncthreads();
    }

    // epilogue: bias + relu (+tf32 round) (+dup)
    const int crow = r8;
    const int ccol = c3 << 1;
#pragma unroll
    for (int i = 0; i < 4; i++) {
        int r0 = m0 + wy * 64 + i * 16 + crow;
        int r1 = r0 + 8;
#pragma unroll
        for (int j = 0; j < 4; j++) {
            int c = n0 + wx * 32 + j * 8 + ccol;
            float b0 = bias[c], b1 = bias[c + 1];
            float2 v0, v1;
            v0.x = fmaxf(acc[i][j][0] + b0, 0.f);
            v0.y = fmaxf(acc[i][j][1] + b1, 0.f);
            v1.x = fmaxf(acc[i][j][2] + b0, 0.f);
            v1.y = fmaxf(acc[i][j][3] + b1, 0.f);
            if (ROUND_OUT) {
                v0.x = roundtf(v0.x); v0.y = roundtf(v0.y);
                v1.x = roundtf(v1.x); v1.y = roundtf(v1.y);
            }
            if (r0 < M) {
                *(float2*)&C[(size_t)r0 * ldc + c] = v0;
                if (DUP) *(float2*)&C2[(size_t)r0 * ldc + c] = v0;
            }
            if (r1 < M) {
                *(float2*)&C[(size_t)r1 * ldc + c] = v1;
                if (DUP) *(float2*)&C2[(size_t)r1 * ldc + c] = v1;
            }
        }
    }
}

// ---------------- pooling + head ----------------
__global__ void zero_pool() {
    int i = blockIdx.x * blockDim.x + threadIdx.x;
    if (i < N_GRAPHS * HID) g_pool[i] = 0.f;
    if (i < N_GRAPHS) g_cnt[i] = 0;
}

__global__ void pool_sum(const int* __restrict__ batch) {
    long long t = (long long)blockIdx.x * blockDim.x + threadIdx.x;
    int node = (int)(t >> 7);
    int f4 = (int)(t & 127);
    if (node >= N_NODES) return;
    int g = batch[node];
    float4 v = *(const float4*)&g_h[(size_t)node * HID + f4 * 4];
    atomicAdd((float4*)&g_pool[(size_t)g * HID + f4 * 4], v);
    if (f4 == 0) atomicAdd(&g_cnt[g], 1);
}

__global__ void pool_div() {
    int i = blockIdx.x * blockDim.x + threadIdx.x;
    if (i >= N_GRAPHS * HID) return;
    int g = i >> 9;
    float c = (float)g_cnt[g];
    g_pool[i] = roundtf(g_pool[i] / fmaxf(c, 1.f));
}

__global__ void head2(const float* __restrict__ w, const float* __restrict__ b,
                      float* __restrict__ out) {
    int g = blockIdx.x;
    int o = threadIdx.x;
    if (o >= 12) return;
    float acc = b[o];
    const float* row = g_p1 + (size_t)g * 256;
#pragma unroll 8
    for (int k = 0; k < 256; k++) acc = fmaf(row[k], w[k * 12 + o], acc);
    out[(size_t)g * 12 + o] = acc;
}

// ---------------- launch ----------------
extern "C" void kernel_launch(void* const* d_in, const int* in_sizes, int n_in,
                              void* d_out, int out_size) {
    const float* x = (const float*)d_in[0];
    const int* ei = (const int*)d_in[1];
    const int* src = ei;
    const int* dst = ei + N_EDGES;
    const int* batch = (const int*)d_in[2];
    const float* c1w1 = (const float*)d_in[3];
    const float* c1b1 = (const float*)d_in[4];
    const float* c1w2 = (const float*)d_in[5];
    const float* c1b2 = (const float*)d_in[6];
    const float* c2w1 = (const float*)d_in[7];
    const float* c2b1 = (const float*)d_in[8];
    const float* c2w2 = (const float*)d_in[9];
    const float* c2b2 = (const float*)d_in[10];
    const float* c3w1 = (const float*)d_in[11];
    const float* c3b1 = (const float*)d_in[12];
    const float* c3w2 = (const float*)d_in[13];
    const float* c3b2 = (const float*)d_in[14];
    const float* lw1 = (const float*)d_in[15];
    const float* lb1 = (const float*)d_in[16];
    const float* lw2 = (const float*)d_in[17];
    const float* lb2 = (const float*)d_in[18];
    float* out = (float*)d_out;

    float *p_h, *p_t, *p_m, *p_pool, *p_p1, *p_wt;
    cudaGetSymbolAddress((void**)&p_h, g_h);
    cudaGetSymbolAddress((void**)&p_t, g_t);
    cudaGetSymbolAddress((void**)&p_m, g_m);
    cudaGetSymbolAddress((void**)&p_pool, g_pool);
    cudaGetSymbolAddress((void**)&p_p1, g_p1);
    cudaGetSymbolAddress((void**)&p_wt, g_wt);

    float* t_c1w2 = p_wt + 0 * 262144;
    float* t_c2w1 = p_wt + 1 * 262144;
    float* t_c2w2 = p_wt + 2 * 262144;
    float* t_c3w1 = p_wt + 3 * 262144;
    float* t_c3w2 = p_wt + 4 * 262144;
    float* t_lw1  = p_wt + 5 * 262144;

    cudaFuncSetAttribute(gemm_ca<true, false>, cudaFuncAttributeMaxDynamicSharedMemorySize, GSM_BYTES);
    cudaFuncSetAttribute(gemm_ca<false, true>, cudaFuncAttributeMaxDynamicSharedMemorySize, GSM_BYTES);
    cudaFuncSetAttribute(gemm_ca<false, false>, cudaFuncAttributeMaxDynamicSharedMemorySize, GSM_BYTES);

    // weight transposes ([K,N] -> [N,K], tf32-rounded)
    {
        dim3 b(32, 8);
        transposeKN<<<dim3(16, 16), b>>>(c1w2, t_c1w2, 512, 512);
        transposeKN<<<dim3(16, 16), b>>>(c2w1, t_c2w1, 512, 512);
        transposeKN<<<dim3(16, 16), b>>>(c2w2, t_c2w2, 512, 512);
        transposeKN<<<dim3(16, 16), b>>>(c3w1, t_c3w1, 512, 512);
        transposeKN<<<dim3(16, 16), b>>>(c3w2, t_c3w2, 512, 512);
        transposeKN<<<dim3(8, 16), b>>>(lw1, t_lw1, 512, 256);
    }

    const dim3 gg(4, (N_NODES + 127) / 128);  // 512/128 n-blocks
    const dim3 hg(2, N_GRAPHS / 128);
    const int RT_GRID = (int)(((size_t)N_NODES * HID / 4 + 255) / 256);

    // ---- layer 1 ----
    copy_x7<<<(N_NODES * 7 + 255) / 256, 256>>>(x);
    edge_agg7<<<(int)(((long long)N_EDGES * 8 + 255) / 256), 256>>>(src, dst, x);
    mlp_in7<<<2048, 256>>>(c1w1, c1b1);  // g_m tf32-rounded
    gemm_ca<false, true><<<gg, 256, GSM_BYTES>>>(N_NODES, HID, HID, p_m, t_c1w2, c1b2, p_h, p_t);

    // ---- layer 2 ----
    edge_agg512<<<(int)(((long long)N_EDGES * 32 + 255) / 256), 256>>>(src, dst);
    round_t<<<RT_GRID, 256>>>();
    gemm_ca<true, false><<<gg, 256, GSM_BYTES>>>(N_NODES, HID, HID, p_t, t_c2w1, c2b1, p_m, nullptr);
    gemm_ca<false, true><<<gg, 256, GSM_BYTES>>>(N_NODES, HID, HID, p_m, t_c2w2, c2b2, p_h, p_t);

    // ---- layer 3 ----
    edge_agg512<<<(int)(((long long)N_EDGES * 32 + 255) / 256), 256>>>(src, dst);
    round_t<<<RT_GRID, 256>>>();
    gemm_ca<true, false><<<gg, 256, GSM_BYTES>>>(N_NODES, HID, HID, p_t, t_c3w1, c3b1, p_m, nullptr);
    gemm_ca<false, false><<<gg, 256, GSM_BYTES>>>(N_NODES, HID, HID, p_m, t_c3w2, c3b2, p_h, nullptr);

    // ---- mean pool ----
    zero_pool<<<(N_GRAPHS * HID + 255) / 256, 256>>>();
    pool_sum<<<(int)(((long long)N_NODES * 128 + 255) / 256), 256>>>(batch);
    pool_div<<<(N_GRAPHS * HID + 255) / 256, 256>>>();

    // ---- head ----
    gemm_ca<false, false><<<hg, 256, GSM_BYTES>>>(N_GRAPHS, HID, 256, p_pool, t_lw1, lb1, p_p1, nullptr);
    head2<<<N_GRAPHS, 32>>>(lw2, lb2, out);
}

// round 6
// speedup vs baseline: 4.4898x; 1.6093x over previous
#include <cuda_runtime.h>
#include <cuda_bf16.h>
#include <cstdint>
#include <cstddef>

#define N_NODES 100000
#define N_EDGES 1600000
#define N_GRAPHS 4096
#define HID 512

// ---------------- scratch (device globals; allocation-free) ----------------
__device__ float g_h[(size_t)N_NODES * HID];
__device__ float g_t[(size_t)N_NODES * HID];
__device__ float g_m[(size_t)N_NODES * HID];
__device__ float g_h7[(size_t)N_NODES * 7];
__device__ float g_pool[(size_t)N_GRAPHS * HID];
__device__ float g_p1[(size_t)N_GRAPHS * 256];
__device__ float g_wt[5 * 512 * 512 + 256 * 512];  // [N,K] transposed tf32-rounded weights
// CSR scratch
__device__ int g_deg[N_NODES];
__device__ int g_rows[N_NODES + 1];
__device__ int g_cur[N_NODES];
__device__ int g_csr[N_EDGES];
__device__ int g_gstart[N_GRAPHS + 1];

__device__ __forceinline__ uint32_t f2tf32(float x) {
    uint32_t r;
    asm("cvt.rna.tf32.f32 %0, %1;" : "=r"(r) : "f"(x));
    return r;
}
__device__ __forceinline__ float roundtf(float x) { return __uint_as_float(f2tf32(x)); }

// ---------------- CSR build ----------------
__global__ void deg_zero() {
    int i = blockIdx.x * blockDim.x + threadIdx.x;
    if (i < N_NODES) g_deg[i] = 0;
}

__global__ void deg_count(const int* __restrict__ dst) {
    int e = blockIdx.x * blockDim.x + threadIdx.x;
    if (e < N_EDGES) atomicAdd(&g_deg[dst[e]], 1);
}

// single-block chunked exclusive scan of g_deg -> g_rows (and copy to g_cur)
__global__ __launch_bounds__(1024) void deg_scan() {
    __shared__ int s[1024];
    __shared__ int carry;
    const int tid = threadIdx.x;
    if (tid == 0) carry = 0;
    __syncthreads();
    for (int base = 0; base < N_NODES; base += 1024) {
        int v = (base + tid < N_NODES) ? g_deg[base + tid] : 0;
        s[tid] = v;
        __syncthreads();
#pragma unroll
        for (int off = 1; off < 1024; off <<= 1) {
            int t = (tid >= off) ? s[tid - off] : 0;
            __syncthreads();
            s[tid] += t;
            __syncthreads();
        }
        int incl = s[tid];
        int excl = incl - v;
        if (base + tid < N_NODES) {
            int r = carry + excl;
            g_rows[base + tid] = r;
            g_cur[base + tid] = r;
        }
        __syncthreads();
        if (tid == 1023) carry += incl;
        __syncthreads();
    }
    if (tid == 0) g_rows[N_NODES] = carry;
}

__global__ void csr_scatter(const int* __restrict__ src, const int* __restrict__ dst) {
    int e = blockIdx.x * blockDim.x + threadIdx.x;
    if (e >= N_EDGES) return;
    int pos = atomicAdd(&g_cur[dst[e]], 1);
    g_csr[pos] = src[e];
}

// per-graph node ranges (batch is sorted ascending)
__global__ void graph_ranges(const int* __restrict__ batch) {
    int g = blockIdx.x * blockDim.x + threadIdx.x;
    if (g > N_GRAPHS) return;
    if (g == N_GRAPHS) { g_gstart[g] = N_NODES; return; }
    // lower_bound: first i with batch[i] >= g
    int lo = 0, hi = N_NODES;
    while (lo < hi) {
        int mid = (lo + hi) >> 1;
        if (batch[mid] < g) lo = mid + 1; else hi = mid;
    }
    g_gstart[g] = lo;
}

// ---------------- layer-1 aggregation (7 feats): t7 = x[i] + sum x[src] ----------------
__global__ void csr_agg7(const float* __restrict__ x) {
    int w = (int)(((long long)blockIdx.x * blockDim.x + threadIdx.x) >> 5);
    int lane = threadIdx.x & 31;
    if (w >= N_NODES) return;
    int beg = g_rows[w], end = g_rows[w + 1];
    float a[7];
#pragma unroll
    for (int k = 0; k < 7; k++) a[k] = (lane == 0) ? x[(size_t)w * 7 + k] : 0.f;
    for (int e = beg + lane; e < end; e += 32) {
        int s = g_csr[e];
#pragma unroll
        for (int k = 0; k < 7; k++) a[k] += x[(size_t)s * 7 + k];
    }
#pragma unroll
    for (int off = 16; off; off >>= 1)
#pragma unroll
        for (int k = 0; k < 7; k++) a[k] += __shfl_xor_sync(0xFFFFFFFF, a[k], off);
    if (lane == 0) {
#pragma unroll
        for (int k = 0; k < 7; k++) g_h7[(size_t)w * 7 + k] = a[k];
    }
}

// g_m = round_tf32(relu(g_h7 @ w1 + b1)) — exact fp32 math
__global__ __launch_bounds__(256) void mlp_in7(const float* __restrict__ w,
                                               const float* __restrict__ bias) {
    __shared__ float sw[7][512];
    __shared__ float sb[512];
    for (int i = threadIdx.x; i < 7 * 512; i += 256) ((float*)sw)[i] = w[i];
    for (int i = threadIdx.x; i < 512; i += 256) sb[i] = bias[i];
    __syncthreads();
    for (int r = blockIdx.x; r < N_NODES; r += gridDim.x) {
        float h[7];
#pragma unroll
        for (int k = 0; k < 7; k++) h[k] = g_h7[(size_t)r * 7 + k];
#pragma unroll
        for (int jj = 0; jj < 2; jj++) {
            int j = threadIdx.x + jj * 256;
            float acc = sb[j];
#pragma unroll
            for (int k = 0; k < 7; k++) acc = fmaf(h[k], sw[k][j], acc);
            g_m[(size_t)r * 512 + j] = roundtf(fmaxf(acc, 0.f));
        }
    }
}

// ---------------- 512-wide aggregation: g_t[i] = round(g_h[i] + sum g_h[src]) ----------------
__global__ __launch_bounds__(256) void csr_agg512() {
    int w = (int)(((long long)blockIdx.x * blockDim.x + threadIdx.x) >> 5);
    int lane = threadIdx.x & 31;
    if (w >= N_NODES) return;
    int beg = g_rows[w], end = g_rows[w + 1];

    const float4* self = (const float4*)(g_h + (size_t)w * HID);
    float4 acc[4];
#pragma unroll
    for (int i = 0; i < 4; i++) acc[i] = self[lane + 32 * i];

    int e = beg;
    for (; e + 2 <= end; e += 2) {
        int s0 = g_csr[e], s1 = g_csr[e + 1];
        const float4* x0 = (const float4*)(g_h + (size_t)s0 * HID);
        const float4* x1 = (const float4*)(g_h + (size_t)s1 * HID);
        float4 v0[4], v1[4];
#pragma unroll
        for (int i = 0; i < 4; i++) v0[i] = x0[lane + 32 * i];
#pragma unroll
        for (int i = 0; i < 4; i++) v1[i] = x1[lane + 32 * i];
#pragma unroll
        for (int i = 0; i < 4; i++) {
            acc[i].x += v0[i].x + v1[i].x;
            acc[i].y += v0[i].y + v1[i].y;
            acc[i].z += v0[i].z + v1[i].z;
            acc[i].w += v0[i].w + v1[i].w;
        }
    }
    if (e < end) {
        int s0 = g_csr[e];
        const float4* x0 = (const float4*)(g_h + (size_t)s0 * HID);
#pragma unroll
        for (int i = 0; i < 4; i++) {
            float4 v = x0[lane + 32 * i];
            acc[i].x += v.x; acc[i].y += v.y; acc[i].z += v.z; acc[i].w += v.w;
        }
    }

    float4* outp = (float4*)(g_t + (size_t)w * HID);
#pragma unroll
    for (int i = 0; i < 4; i++) {
        acc[i].x = roundtf(acc[i].x); acc[i].y = roundtf(acc[i].y);
        acc[i].z = roundtf(acc[i].z); acc[i].w = roundtf(acc[i].w);
        outp[lane + 32 * i] = acc[i];
    }
}

// transpose [K,N] -> [N,K], tf32-round
__global__ void transposeKN(const float* __restrict__ in, float* __restrict__ outp,
                            int K, int N) {
    __shared__ float t[32][33];
    int n0 = blockIdx.x * 32, k0 = blockIdx.y * 32;
    int tx = threadIdx.x, ty = threadIdx.y;  // block (32,8)
#pragma unroll
    for (int i = 0; i < 4; i++)
        t[ty + i * 8][tx] = in[(size_t)(k0 + ty + i * 8) * N + n0 + tx];
    __syncthreads();
#pragma unroll
    for (int i = 0; i < 4; i++)
        outp[(size_t)(n0 + ty + i * 8) * K + k0 + tx] = roundtf(t[tx][ty + i * 8]);
}

// ---------------- TF32 mma.sync GEMM, cp.async 3-stage pipeline ----------------
#define STG_WORDS 8192
#define STG_BYTES (STG_WORDS * 4)
#define GSM_BYTES (3 * STG_BYTES)  // 96 KB

__device__ __forceinline__ void cp16(uint32_t dst, const void* src, int sz) {
    asm volatile("cp.async.cg.shared.global [%0], [%1], 16, %2;"
                 :: "r"(dst), "l"(src), "r"(sz));
}

__device__ __forceinline__ void mma1688(float* d, const float* a, const float* b) {
    asm volatile(
        "mma.sync.aligned.m16n8k8.row.col.f32.tf32.tf32.f32 "
        "{%0,%1,%2,%3},{%4,%5,%6,%7},{%8,%9},{%0,%1,%2,%3};\n"
        : "+f"(d[0]), "+f"(d[1]), "+f"(d[2]), "+f"(d[3])
        : "r"(__float_as_uint(a[0])), "r"(__float_as_uint(a[1])),
          "r"(__float_as_uint(a[2])), "r"(__float_as_uint(a[3])),
          "r"(__float_as_uint(b[0])), "r"(__float_as_uint(b[1])));
}

template <bool ROUND_OUT>
__global__ __launch_bounds__(256) void gemm_ca(
    int M, int K, int ldc,
    const float* __restrict__ A, const float* __restrict__ Bt,
    const float* __restrict__ bias,
    float* __restrict__ C) {
    extern __shared__ __align__(128) float smf[];
    uint32_t smem_u32;
    asm("{ .reg .u64 t; cvta.to.shared.u64 t, %1; cvt.u32.u64 %0, t; }"
        : "=r"(smem_u32) : "l"(smf));

    const int tid = threadIdx.x;
    const int lane = tid & 31;
    const int warp = tid >> 5;
    const int wy = warp & 1;
    const int wx = warp >> 1;
    const int m0 = blockIdx.y * 128;
    const int n0 = blockIdx.x * 128;

    const int cprow = tid >> 3;
    const int cpc4 = tid & 7;
    const int cpswz = (cpc4 ^ (cprow & 7)) << 2;

    const int nks = K >> 5;

    auto issue = [&](int ks) {
        uint32_t sa = smem_u32 + (uint32_t)(ks % 3) * STG_BYTES;
        uint32_t sb = sa + 16384;
#pragma unroll
        for (int q = 0; q < 4; q++) {
            int row = cprow + q * 32;
            int grow = m0 + row;
            const float* src = A + (size_t)(grow < M ? grow : 0) * K + ks * 32 + cpc4 * 4;
            cp16(sa + (uint32_t)(row * 32 + cpswz) * 4, src, grow < M ? 16 : 0);
        }
#pragma unroll
        for (int q = 0; q < 4; q++) {
            int row = cprow + q * 32;
            const float* src = Bt + (size_t)(n0 + row) * K + ks * 32 + cpc4 * 4;
            cp16(sb + (uint32_t)(row * 32 + cpswz) * 4, src, 16);
        }
        asm volatile("cp.async.commit_group;");
    };

    issue(0);
    issue(1);

    float acc[4][4][4];
#pragma unroll
    for (int i = 0; i < 4; i++)
#pragma unroll
        for (int j = 0; j < 4; j++)
#pragma unroll
            for (int r = 0; r < 4; r++) acc[i][j][r] = 0.f;

    const int r8 = lane >> 2;
    const int c3 = lane & 3;

    for (int ks = 0; ks < nks; ks++) {
        if (ks + 2 < nks) issue(ks + 2);
        else asm volatile("cp.async.commit_group;");
        asm volatile("cp.async.wait_group %0;" :: "n"(2));
        __syncthreads();

        const float* sA = smf + (ks % 3) * STG_WORDS;
        const float* sB = sA + 4096;
#pragma unroll
        for (int kk = 0; kk < 4; kk++) {
            float a[4][4];
#pragma unroll
            for (int i = 0; i < 4; i++) {
                int row = wy * 64 + i * 16 + r8;
                int base = row * 32;
                int ch0 = ((kk * 2) ^ r8) * 4 + c3;
                int ch1 = ((kk * 2 + 1) ^ r8) * 4 + c3;
                a[i][0] = sA[base + ch0];
                a[i][1] = sA[base + 256 + ch0];
                a[i][2] = sA[base + ch1];
                a[i][3] = sA[base + 256 + ch1];
            }
            float b[4][2];
#pragma unroll
            for (int j = 0; j < 4; j++) {
                int n = wx * 32 + j * 8 + r8;
                int base = n * 32;
                b[j][0] = sB[base + ((kk * 2) ^ r8) * 4 + c3];
                b[j][1] = sB[base + ((kk * 2 + 1) ^ r8) * 4 + c3];
            }
#pragma unroll
            for (int i = 0; i < 4; i++)
#pragma unroll
                for (int j = 0; j < 4; j++) mma1688(acc[i][j], a[i], b[j]);
        }
        __syncthreads();
    }

    const int crow = r8;
    const int ccol = c3 << 1;
#pragma unroll
    for (int i = 0; i < 4; i++) {
        int r0 = m0 + wy * 64 + i * 16 + crow;
        int r1 = r0 + 8;
#pragma unroll
        for (int j = 0; j < 4; j++) {
            int c = n0 + wx * 32 + j * 8 + ccol;
            float b0 = bias[c], b1 = bias[c + 1];
            float2 v0, v1;
            v0.x = fmaxf(acc[i][j][0] + b0, 0.f);
            v0.y = fmaxf(acc[i][j][1] + b1, 0.f);
            v1.x = fmaxf(acc[i][j][2] + b0, 0.f);
            v1.y = fmaxf(acc[i][j][3] + b1, 0.f);
            if (ROUND_OUT) {
                v0.x = roundtf(v0.x); v0.y = roundtf(v0.y);
                v1.x = roundtf(v1.x); v1.y = roundtf(v1.y);
            }
            if (r0 < M) *(float2*)&C[(size_t)r0 * ldc + c] = v0;
            if (r1 < M) *(float2*)&C[(size_t)r1 * ldc + c] = v1;
        }
    }
}

// ---------------- pooling (batch sorted -> per-graph ranges) + head ----------------
__global__ __launch_bounds__(128) void pool_mean() {
    int g = blockIdx.x;
    int beg = g_gstart[g], end = g_gstart[g + 1];
    float4 acc = make_float4(0.f, 0.f, 0.f, 0.f);
    const int t = threadIdx.x;  // 0..127 (float4 columns)
    for (int n = beg; n < end; n++) {
        float4 v = ((const float4*)(g_h + (size_t)n * HID))[t];
        acc.x += v.x; acc.y += v.y; acc.z += v.z; acc.w += v.w;
    }
    float c = fmaxf((float)(end - beg), 1.f);
    acc.x = roundtf(acc.x / c); acc.y = roundtf(acc.y / c);
    acc.z = roundtf(acc.z / c); acc.w = roundtf(acc.w / c);
    ((float4*)(g_pool + (size_t)g * HID))[t] = acc;
}

__global__ void head2(const float* __restrict__ w, const float* __restrict__ b,
                      float* __restrict__ out) {
    int g = blockIdx.x;
    int o = threadIdx.x;
    if (o >= 12) return;
    float acc = b[o];
    const float* row = g_p1 + (size_t)g * 256;
#pragma unroll 8
    for (int k = 0; k < 256; k++) acc = fmaf(row[k], w[k * 12 + o], acc);
    out[(size_t)g * 12 + o] = acc;
}

// ---------------- launch ----------------
extern "C" void kernel_launch(void* const* d_in, const int* in_sizes, int n_in,
                              void* d_out, int out_size) {
    const float* x = (const float*)d_in[0];
    const int* ei = (const int*)d_in[1];
    const int* src = ei;
    const int* dst = ei + N_EDGES;
    const int* batch = (const int*)d_in[2];
    const float* c1w1 = (const float*)d_in[3];
    const float* c1b1 = (const float*)d_in[4];
    const float* c1w2 = (const float*)d_in[5];
    const float* c1b2 = (const float*)d_in[6];
    const float* c2w1 = (const float*)d_in[7];
    const float* c2b1 = (const float*)d_in[8];
    const float* c2w2 = (const float*)d_in[9];
    const float* c2b2 = (const float*)d_in[10];
    const float* c3w1 = (const float*)d_in[11];
    const float* c3b1 = (const float*)d_in[12];
    const float* c3w2 = (const float*)d_in[13];
    const float* c3b2 = (const float*)d_in[14];
    const float* lw1 = (const float*)d_in[15];
    const float* lb1 = (const float*)d_in[16];
    const float* lw2 = (const float*)d_in[17];
    const float* lb2 = (const float*)d_in[18];
    float* out = (float*)d_out;

    float *p_h, *p_t, *p_m, *p_pool, *p_p1, *p_wt;
    cudaGetSymbolAddress((void**)&p_h, g_h);
    cudaGetSymbolAddress((void**)&p_t, g_t);
    cudaGetSymbolAddress((void**)&p_m, g_m);
    cudaGetSymbolAddress((void**)&p_pool, g_pool);
    cudaGetSymbolAddress((void**)&p_p1, g_p1);
    cudaGetSymbolAddress((void**)&p_wt, g_wt);

    float* t_c1w2 = p_wt + 0 * 262144;
    float* t_c2w1 = p_wt + 1 * 262144;
    float* t_c2w2 = p_wt + 2 * 262144;
    float* t_c3w1 = p_wt + 3 * 262144;
    float* t_c3w2 = p_wt + 4 * 262144;
    float* t_lw1  = p_wt + 5 * 262144;

    cudaFuncSetAttribute(gemm_ca<true>, cudaFuncAttributeMaxDynamicSharedMemorySize, GSM_BYTES);
    cudaFuncSetAttribute(gemm_ca<false>, cudaFuncAttributeMaxDynamicSharedMemorySize, GSM_BYTES);

    // ---- CSR build + graph ranges + weight transposes ----
    deg_zero<<<(N_NODES + 255) / 256, 256>>>();
    deg_count<<<(N_EDGES + 255) / 256, 256>>>(dst);
    deg_scan<<<1, 1024>>>();
    csr_scatter<<<(N_EDGES + 255) / 256, 256>>>(src, dst);
    graph_ranges<<<(N_GRAPHS + 256) / 256, 256>>>(batch);
    {
        dim3 b(32, 8);
        transposeKN<<<dim3(16, 16), b>>>(c1w2, t_c1w2, 512, 512);
        transposeKN<<<dim3(16, 16), b>>>(c2w1, t_c2w1, 512, 512);
        transposeKN<<<dim3(16, 16), b>>>(c2w2, t_c2w2, 512, 512);
        transposeKN<<<dim3(16, 16), b>>>(c3w1, t_c3w1, 512, 512);
        transposeKN<<<dim3(16, 16), b>>>(c3w2, t_c3w2, 512, 512);
        transposeKN<<<dim3(8, 16), b>>>(lw1, t_lw1, 512, 256);
    }

    const dim3 gg(4, (N_NODES + 127) / 128);
    const dim3 hg(2, N_GRAPHS / 128);
    const int AGG_GRID = (N_NODES * 32 + 255) / 256;

    // ---- layer 1 ----
    csr_agg7<<<AGG_GRID, 256>>>(x);
    mlp_in7<<<2048, 256>>>(c1w1, c1b1);
    gemm_ca<false><<<gg, 256, GSM_BYTES>>>(N_NODES, HID, HID, p_m, t_c1w2, c1b2, p_h);

    // ---- layer 2 ----
    csr_agg512<<<AGG_GRID, 256>>>();
    gemm_ca<true><<<gg, 256, GSM_BYTES>>>(N_NODES, HID, HID, p_t, t_c2w1, c2b1, p_m);
    gemm_ca<false><<<gg, 256, GSM_BYTES>>>(N_NODES, HID, HID, p_m, t_c2w2, c2b2, p_h);

    // ---- layer 3 ----
    csr_agg512<<<AGG_GRID, 256>>>();
    gemm_ca<true><<<gg, 256, GSM_BYTES>>>(N_NODES, HID, HID, p_t, t_c3w1, c3b1, p_m);
    gemm_ca<false><<<gg, 256, GSM_BYTES>>>(N_NODES, HID, HID, p_m, t_c3w2, c3b2, p_h);

    // ---- mean pool ----
    pool_mean<<<N_GRAPHS, 128>>>();

    // ---- head ----
    gemm_ca<false><<<hg, 256, GSM_BYTES>>>(N_GRAPHS, HID, 256, p_pool, t_lw1, lb1, p_p1);
    head2<<<N_GRAPHS, 32>>>(lw2, lb2, out);
}

// round 7
// speedup vs baseline: 5.3288x; 1.1869x over previous
#include <cuda_runtime.h>
#include <cuda_bf16.h>
#include <cstdint>
#include <cstddef>

#define N_NODES 100000
#define N_EDGES 1600000
#define N_GRAPHS 4096
#define HID 512
#define NCHUNK ((N_NODES + 1023) / 1024)

// ---------------- scratch (device globals; allocation-free) ----------------
__device__ float g_h[(size_t)N_NODES * HID];
__device__ float g_t[(size_t)N_NODES * HID];
__device__ float g_m[(size_t)N_NODES * HID];
__device__ float g_h7[(size_t)N_NODES * 7];
__device__ float g_pool[(size_t)N_GRAPHS * HID];
__device__ float g_p1[(size_t)N_GRAPHS * 256];
__device__ float g_wt[5 * 512 * 512 + 256 * 512];  // [N,K] transposed tf32-rounded weights
// CSR scratch
__device__ int g_deg[N_NODES];
__device__ int g_rows[N_NODES + 1];
__device__ int g_cur[N_NODES];
__device__ int g_csr[N_EDGES];
__device__ int g_gstart[N_GRAPHS + 1];
__device__ int g_bsum[NCHUNK];
__device__ int g_boff[NCHUNK];

__device__ __forceinline__ uint32_t f2tf32(float x) {
    uint32_t r;
    asm("cvt.rna.tf32.f32 %0, %1;" : "=r"(r) : "f"(x));
    return r;
}
__device__ __forceinline__ float roundtf(float x) { return __uint_as_float(f2tf32(x)); }

// ---------------- CSR build ----------------
__global__ void deg_count(const int* __restrict__ dst) {
    int e = blockIdx.x * blockDim.x + threadIdx.x;
    if (e < N_EDGES) atomicAdd(&g_deg[dst[e]], 1);
}

// phase 1: per-block exclusive scan (no carry), block sums out
__global__ __launch_bounds__(1024) void scan1() {
    __shared__ int s[1024];
    const int b = blockIdx.x;
    const int tid = threadIdx.x;
    const int i = b * 1024 + tid;
    int v = (i < N_NODES) ? g_deg[i] : 0;
    s[tid] = v;
    __syncthreads();
#pragma unroll
    for (int off = 1; off < 1024; off <<= 1) {
        int t = (tid >= off) ? s[tid - off] : 0;
        __syncthreads();
        s[tid] += t;
        __syncthreads();
    }
    if (i < N_NODES) g_rows[i] = s[tid] - v;  // exclusive, block-local
    if (tid == 1023) g_bsum[b] = s[1023];
}

// phase 2: carry scan over block sums (tiny)
__global__ void scan2() {
    if (threadIdx.x == 0) {
        int c = 0;
        for (int b = 0; b < NCHUNK; b++) { g_boff[b] = c; c += g_bsum[b]; }
        g_rows[N_NODES] = c;
    }
}

// phase 3: apply block offsets
__global__ __launch_bounds__(1024) void scan3() {
    const int b = blockIdx.x;
    const int i = b * 1024 + threadIdx.x;
    if (i < N_NODES) {
        int r = g_rows[i] + g_boff[b];
        g_rows[i] = r;
        g_cur[i] = r;
    }
}

__global__ void csr_scatter(const int* __restrict__ src, const int* __restrict__ dst) {
    int e = blockIdx.x * blockDim.x + threadIdx.x;
    if (e >= N_EDGES) return;
    int pos = atomicAdd(&g_cur[dst[e]], 1);
    g_csr[pos] = src[e];
}

// per-graph node ranges (batch is sorted ascending)
__global__ void graph_ranges(const int* __restrict__ batch) {
    int g = blockIdx.x * blockDim.x + threadIdx.x;
    if (g > N_GRAPHS) return;
    if (g == N_GRAPHS) { g_gstart[g] = N_NODES; return; }
    int lo = 0, hi = N_NODES;
    while (lo < hi) {
        int mid = (lo + hi) >> 1;
        if (batch[mid] < g) lo = mid + 1; else hi = mid;
    }
    g_gstart[g] = lo;
}

// ---------------- layer-1 aggregation (7 feats) ----------------
__global__ void csr_agg7(const float* __restrict__ x) {
    int w = (int)(((long long)blockIdx.x * blockDim.x + threadIdx.x) >> 5);
    int lane = threadIdx.x & 31;
    if (w >= N_NODES) return;
    int beg = g_rows[w], end = g_rows[w + 1];
    float a[7];
#pragma unroll
    for (int k = 0; k < 7; k++) a[k] = (lane == 0) ? x[(size_t)w * 7 + k] : 0.f;
    for (int e = beg + lane; e < end; e += 32) {
        int s = g_csr[e];
#pragma unroll
        for (int k = 0; k < 7; k++) a[k] += x[(size_t)s * 7 + k];
    }
#pragma unroll
    for (int off = 16; off; off >>= 1)
#pragma unroll
        for (int k = 0; k < 7; k++) a[k] += __shfl_xor_sync(0xFFFFFFFF, a[k], off);
    if (lane == 0) {
#pragma unroll
        for (int k = 0; k < 7; k++) g_h7[(size_t)w * 7 + k] = a[k];
    }
}

// g_m = round_tf32(relu(g_h7 @ w1 + b1)) — exact fp32 math
__global__ __launch_bounds__(256) void mlp_in7(const float* __restrict__ w,
                                               const float* __restrict__ bias) {
    __shared__ float sw[7][512];
    __shared__ float sb[512];
    for (int i = threadIdx.x; i < 7 * 512; i += 256) ((float*)sw)[i] = w[i];
    for (int i = threadIdx.x; i < 512; i += 256) sb[i] = bias[i];
    __syncthreads();
    for (int r = blockIdx.x; r < N_NODES; r += gridDim.x) {
        float h[7];
#pragma unroll
        for (int k = 0; k < 7; k++) h[k] = g_h7[(size_t)r * 7 + k];
#pragma unroll
        for (int jj = 0; jj < 2; jj++) {
            int j = threadIdx.x + jj * 256;
            float acc = sb[j];
#pragma unroll
            for (int k = 0; k < 7; k++) acc = fmaf(h[k], sw[k][j], acc);
            g_m[(size_t)r * 512 + j] = roundtf(fmaxf(acc, 0.f));
        }
    }
}

// ---------------- L2-blocked 512-wide aggregation ----------------
// blockIdx.y = column chunk (0..3), 128 floats each: per-chunk working set
// = 100000 * 128 * 4B = 51 MB < L2, so gathers hit L2 after first touch.
// g_t[i, chunk] = round_tf32(g_h[i, chunk] + sum_src g_h[src, chunk])
__global__ __launch_bounds__(256) void csr_agg512_chunk() {
    int w = (int)(((long long)blockIdx.x * blockDim.x + threadIdx.x) >> 5);
    int lane = threadIdx.x & 31;
    if (w >= N_NODES) return;
    const int off = blockIdx.y * 128 + lane * 4;
    const int beg = g_rows[w], end = g_rows[w + 1];
    const float* base = g_h + off;

    float4 acc = *(const float4*)(base + (size_t)w * HID);

    int e = beg;
    for (; e + 4 <= end; e += 4) {
        int s0 = g_csr[e], s1 = g_csr[e + 1], s2 = g_csr[e + 2], s3 = g_csr[e + 3];
        float4 v0 = *(const float4*)(base + (size_t)s0 * HID);
        float4 v1 = *(const float4*)(base + (size_t)s1 * HID);
        float4 v2 = *(const float4*)(base + (size_t)s2 * HID);
        float4 v3 = *(const float4*)(base + (size_t)s3 * HID);
        acc.x += v0.x + v1.x + v2.x + v3.x;
        acc.y += v0.y + v1.y + v2.y + v3.y;
        acc.z += v0.z + v1.z + v2.z + v3.z;
        acc.w += v0.w + v1.w + v2.w + v3.w;
    }
    for (; e < end; e++) {
        int s0 = g_csr[e];
        float4 v = *(const float4*)(base + (size_t)s0 * HID);
        acc.x += v.x; acc.y += v.y; acc.z += v.z; acc.w += v.w;
    }

    acc.x = roundtf(acc.x); acc.y = roundtf(acc.y);
    acc.z = roundtf(acc.z); acc.w = roundtf(acc.w);
    *(float4*)(g_t + (size_t)w * HID + off) = acc;
}

// transpose [K,N] -> [N,K], tf32-round
__global__ void transposeKN(const float* __restrict__ in, float* __restrict__ outp,
                            int K, int N) {
    __shared__ float t[32][33];
    int n0 = blockIdx.x * 32, k0 = blockIdx.y * 32;
    int tx = threadIdx.x, ty = threadIdx.y;  // block (32,8)
#pragma unroll
    for (int i = 0; i < 4; i++)
        t[ty + i * 8][tx] = in[(size_t)(k0 + ty + i * 8) * N + n0 + tx];
    __syncthreads();
#pragma unroll
    for (int i = 0; i < 4; i++)
        outp[(size_t)(n0 + ty + i * 8) * K + k0 + tx] = roundtf(t[tx][ty + i * 8]);
}

// ---------------- TF32 mma.sync GEMM, cp.async 3-stage pipeline ----------------
#define STG_WORDS 8192
#define STG_BYTES (STG_WORDS * 4)
#define GSM_BYTES (3 * STG_BYTES)  // 96 KB

__device__ __forceinline__ void cp16(uint32_t dst, const void* src, int sz) {
    asm volatile("cp.async.cg.shared.global [%0], [%1], 16, %2;"
                 :: "r"(dst), "l"(src), "r"(sz));
}

__device__ __forceinline__ void mma1688(float* d, const float* a, const float* b) {
    asm volatile(
        "mma.sync.aligned.m16n8k8.row.col.f32.tf32.tf32.f32 "
        "{%0,%1,%2,%3},{%4,%5,%6,%7},{%8,%9},{%0,%1,%2,%3};\n"
        : "+f"(d[0]), "+f"(d[1]), "+f"(d[2]), "+f"(d[3])
        : "r"(__float_as_uint(a[0])), "r"(__float_as_uint(a[1])),
          "r"(__float_as_uint(a[2])), "r"(__float_as_uint(a[3])),
          "r"(__float_as_uint(b[0])), "r"(__float_as_uint(b[1])));
}

template <bool ROUND_OUT>
__global__ __launch_bounds__(256) void gemm_ca(
    int M, int K, int ldc,
    const float* __restrict__ A, const float* __restrict__ Bt,
    const float* __restrict__ bias,
    float* __restrict__ C) {
    extern __shared__ __align__(128) float smf[];
    uint32_t smem_u32;
    asm("{ .reg .u64 t; cvta.to.shared.u64 t, %1; cvt.u32.u64 %0, t; }"
        : "=r"(smem_u32) : "l"(smf));

    const int tid = threadIdx.x;
    const int lane = tid & 31;
    const int warp = tid >> 5;
    const int wy = warp & 1;
    const int wx = warp >> 1;
    const int m0 = blockIdx.y * 128;
    const int n0 = blockIdx.x * 128;

    const int cprow = tid >> 3;
    const int cpc4 = tid & 7;
    const int cpswz = (cpc4 ^ (cprow & 7)) << 2;

    const int nks = K >> 5;

    auto issue = [&](int ks) {
        uint32_t sa = smem_u32 + (uint32_t)(ks % 3) * STG_BYTES;
        uint32_t sb = sa + 16384;
#pragma unroll
        for (int q = 0; q < 4; q++) {
            int row = cprow + q * 32;
            int grow = m0 + row;
            const float* src = A + (size_t)(grow < M ? grow : 0) * K + ks * 32 + cpc4 * 4;
            cp16(sa + (uint32_t)(row * 32 + cpswz) * 4, src, grow < M ? 16 : 0);
        }
#pragma unroll
        for (int q = 0; q < 4; q++) {
            int row = cprow + q * 32;
            const float* src = Bt + (size_t)(n0 + row) * K + ks * 32 + cpc4 * 4;
            cp16(sb + (uint32_t)(row * 32 + cpswz) * 4, src, 16);
        }
        asm volatile("cp.async.commit_group;");
    };

    issue(0);
    issue(1);

    float acc[4][4][4];
#pragma unroll
    for (int i = 0; i < 4; i++)
#pragma unroll
        for (int j = 0; j < 4; j++)
#pragma unroll
            for (int r = 0; r < 4; r++) acc[i][j][r] = 0.f;

    const int r8 = lane >> 2;
    const int c3 = lane & 3;

    for (int ks = 0; ks < nks; ks++) {
        if (ks + 2 < nks) issue(ks + 2);
        else asm volatile("cp.async.commit_group;");
        asm volatile("cp.async.wait_group %0;" :: "n"(2));
        __syncthreads();

        const float* sA = smf + (ks % 3) * STG_WORDS;
        const float* sB = sA + 4096;
#pragma unroll
        for (int kk = 0; kk < 4; kk++) {
            float a[4][4];
#pragma unroll
            for (int i = 0; i < 4; i++) {
                int row = wy * 64 + i * 16 + r8;
                int base = row * 32;
                int ch0 = ((kk * 2) ^ r8) * 4 + c3;
                int ch1 = ((kk * 2 + 1) ^ r8) * 4 + c3;
                a[i][0] = sA[base + ch0];
                a[i][1] = sA[base + 256 + ch0];
                a[i][2] = sA[base + ch1];
                a[i][3] = sA[base + 256 + ch1];
            }
            float b[4][2];
#pragma unroll
            for (int j = 0; j < 4; j++) {
                int n = wx * 32 + j * 8 + r8;
                int base = n * 32;
                b[j][0] = sB[base + ((kk * 2) ^ r8) * 4 + c3];
                b[j][1] = sB[base + ((kk * 2 + 1) ^ r8) * 4 + c3];
            }
#pragma unroll
            for (int i = 0; i < 4; i++)
#pragma unroll
                for (int j = 0; j < 4; j++) mma1688(acc[i][j], a[i], b[j]);
        }
        __syncthreads();
    }

    const int crow = r8;
    const int ccol = c3 << 1;
#pragma unroll
    for (int i = 0; i < 4; i++) {
        int r0 = m0 + wy * 64 + i * 16 + crow;
        int r1 = r0 + 8;
#pragma unroll
        for (int j = 0; j < 4; j++) {
            int c = n0 + wx * 32 + j * 8 + ccol;
            float b0 = bias[c], b1 = bias[c + 1];
            float2 v0, v1;
            v0.x = fmaxf(acc[i][j][0] + b0, 0.f);
            v0.y = fmaxf(acc[i][j][1] + b1, 0.f);
            v1.x = fmaxf(acc[i][j][2] + b0, 0.f);
            v1.y = fmaxf(acc[i][j][3] + b1, 0.f);
            if (ROUND_OUT) {
                v0.x = roundtf(v0.x); v0.y = roundtf(v0.y);
                v1.x = roundtf(v1.x); v1.y = roundtf(v1.y);
            }
            if (r0 < M) *(float2*)&C[(size_t)r0 * ldc + c] = v0;
            if (r1 < M) *(float2*)&C[(size_t)r1 * ldc + c] = v1;
        }
    }
}

// ---------------- pooling + head ----------------
__global__ __launch_bounds__(128) void pool_mean() {
    int g = blockIdx.x;
    int beg = g_gstart[g], end = g_gstart[g + 1];
    float4 acc = make_float4(0.f, 0.f, 0.f, 0.f);
    const int t = threadIdx.x;
    for (int n = beg; n < end; n++) {
        float4 v = ((const float4*)(g_h + (size_t)n * HID))[t];
        acc.x += v.x; acc.y += v.y; acc.z += v.z; acc.w += v.w;
    }
    float c = fmaxf((float)(end - beg), 1.f);
    acc.x = roundtf(acc.x / c); acc.y = roundtf(acc.y / c);
    acc.z = roundtf(acc.z / c); acc.w = roundtf(acc.w / c);
    ((float4*)(g_pool + (size_t)g * HID))[t] = acc;
}

__global__ void head2(const float* __restrict__ w, const float* __restrict__ b,
                      float* __restrict__ out) {
    int g = blockIdx.x;
    int o = threadIdx.x;
    if (o >= 12) return;
    float acc = b[o];
    const float* row = g_p1 + (size_t)g * 256;
#pragma unroll 8
    for (int k = 0; k < 256; k++) acc = fmaf(row[k], w[k * 12 + o], acc);
    out[(size_t)g * 12 + o] = acc;
}

// ---------------- launch ----------------
extern "C" void kernel_launch(void* const* d_in, const int* in_sizes, int n_in,
                              void* d_out, int out_size) {
    const float* x = (const float*)d_in[0];
    const int* ei = (const int*)d_in[1];
    const int* src = ei;
    const int* dst = ei + N_EDGES;
    const int* batch = (const int*)d_in[2];
    const float* c1w1 = (const float*)d_in[3];
    const float* c1b1 = (const float*)d_in[4];
    const float* c1w2 = (const float*)d_in[5];
    const float* c1b2 = (const float*)d_in[6];
    const float* c2w1 = (const float*)d_in[7];
    const float* c2b1 = (const float*)d_in[8];
    const float* c2w2 = (const float*)d_in[9];
    const float* c2b2 = (const float*)d_in[10];
    const float* c3w1 = (const float*)d_in[11];
    const float* c3b1 = (const float*)d_in[12];
    const float* c3w2 = (const float*)d_in[13];
    const float* c3b2 = (const float*)d_in[14];
    const float* lw1 = (const float*)d_in[15];
    const float* lb1 = (const float*)d_in[16];
    const float* lw2 = (const float*)d_in[17];
    const float* lb2 = (const float*)d_in[18];
    float* out = (float*)d_out;

    float *p_h, *p_t, *p_m, *p_pool, *p_p1, *p_wt;
    cudaGetSymbolAddress((void**)&p_h, g_h);
    cudaGetSymbolAddress((void**)&p_t, g_t);
    cudaGetSymbolAddress((void**)&p_m, g_m);
    cudaGetSymbolAddress((void**)&p_pool, g_pool);
    cudaGetSymbolAddress((void**)&p_p1, g_p1);
    cudaGetSymbolAddress((void**)&p_wt, g_wt);

    int* p_deg;
    cudaGetSymbolAddress((void**)&p_deg, g_deg);

    float* t_c1w2 = p_wt + 0 * 262144;
    float* t_c2w1 = p_wt + 1 * 262144;
    float* t_c2w2 = p_wt + 2 * 262144;
    float* t_c3w1 = p_wt + 3 * 262144;
    float* t_c3w2 = p_wt + 4 * 262144;
    float* t_lw1  = p_wt + 5 * 262144;

    cudaFuncSetAttribute(gemm_ca<true>, cudaFuncAttributeMaxDynamicSharedMemorySize, GSM_BYTES);
    cudaFuncSetAttribute(gemm_ca<false>, cudaFuncAttributeMaxDynamicSharedMemorySize, GSM_BYTES);

    // ---- CSR build + graph ranges + weight transposes ----
    cudaMemsetAsync(p_deg, 0, N_NODES * sizeof(int));
    deg_count<<<(N_EDGES + 255) / 256, 256>>>(dst);
    scan1<<<NCHUNK, 1024>>>();
    scan2<<<1, 32>>>();
    scan3<<<NCHUNK, 1024>>>();
    csr_scatter<<<(N_EDGES + 255) / 256, 256>>>(src, dst);
    graph_ranges<<<(N_GRAPHS + 256) / 256, 256>>>(batch);
    {
        dim3 b(32, 8);
        transposeKN<<<dim3(16, 16), b>>>(c1w2, t_c1w2, 512, 512);
        transposeKN<<<dim3(16, 16), b>>>(c2w1, t_c2w1, 512, 512);
        transposeKN<<<dim3(16, 16), b>>>(c2w2, t_c2w2, 512, 512);
        transposeKN<<<dim3(16, 16), b>>>(c3w1, t_c3w1, 512, 512);
        transposeKN<<<dim3(16, 16), b>>>(c3w2, t_c3w2, 512, 512);
        transposeKN<<<dim3(8, 16), b>>>(lw1, t_lw1, 512, 256);
    }

    const dim3 gg(4, (N_NODES + 127) / 128);
    const dim3 hg(2, N_GRAPHS / 128);
    const dim3 agg_grid((N_NODES * 32 + 255) / 256, 4);

    // ---- layer 1 ----
    csr_agg7<<<(N_NODES * 32 + 255) / 256, 256>>>(x);
    mlp_in7<<<2048, 256>>>(c1w1, c1b1);
    gemm_ca<false><<<gg, 256, GSM_BYTES>>>(N_NODES, HID, HID, p_m, t_c1w2, c1b2, p_h);

    // ---- layer 2 ----
    csr_agg512_chunk<<<agg_grid, 256>>>();
    gemm_ca<true><<<gg, 256, GSM_BYTES>>>(N_NODES, HID, HID, p_t, t_c2w1, c2b1, p_m);
    gemm_ca<false><<<gg, 256, GSM_BYTES>>>(N_NODES, HID, HID, p_m, t_c2w2, c2b2, p_h);

    // ---- layer 3 ----
    csr_agg512_chunk<<<agg_grid, 256>>>();
    gemm_ca<true><<<gg, 256, GSM_BYTES>>>(N_NODES, HID, HID, p_t, t_c3w1, c3b1, p_m);
    gemm_ca<false><<<gg, 256, GSM_BYTES>>>(N_NODES, HID, HID, p_m, t_c3w2, c3b2, p_h);

    // ---- mean pool ----
    pool_mean<<<N_GRAPHS, 128>>>();

    // ---- head ----
    gemm_ca<false><<<hg, 256, GSM_BYTES>>>(N_GRAPHS, HID, 256, p_pool, t_lw1, lb1, p_p1);
    head2<<<N_GRAPHS, 32>>>(lw2, lb2, out);
}